// round 1
// baseline (speedup 1.0000x reference)
#include <cuda_runtime.h>

#define S 8192
#define E 1024
#define H 16
#define D 64
#define E3 3072

// Scratch (allocation-free rule: __device__ globals)
__device__ __align__(128) float g_Q[H * S * D];
__device__ __align__(128) float g_K[H * S * D];
__device__ __align__(128) float g_V[H * S * D];
__device__ __align__(128) float g_A[S * E];   // attention output accum, [s][h*D+d]

// ---------------------------------------------------------------------------
// QKV projection: Y[m][n] = sum_k X[m][k]*Wqkv[n][k] + b[n], scattered to Q/K/V
// Tile 64x64x16, 256 threads, 4x4 microtile.
// ---------------------------------------------------------------------------
__global__ __launch_bounds__(256) void qkv_gemm_kernel(
    const float* __restrict__ X, const float* __restrict__ W,
    const float* __restrict__ bias) {
  __shared__ float As[16][64];
  __shared__ float Bs[16][64];
  const int bm = blockIdx.y * 64;
  const int bn = blockIdx.x * 64;
  const int tid = threadIdx.x;
  const int lr = tid >> 2;            // 0..63
  const int lk = (tid & 3) << 2;      // 0,4,8,12
  const int ty = tid >> 4;            // 0..15
  const int tx = tid & 15;            // 0..15

  float acc[4][4] = {};
  const float* Xp = X + (size_t)(bm + lr) * E + lk;
  const float* Wp = W + (size_t)(bn + lr) * E + lk;

  for (int k0 = 0; k0 < E; k0 += 16) {
    float4 av = *(const float4*)(Xp + k0);
    float4 bv = *(const float4*)(Wp + k0);
    __syncthreads();
    As[lk + 0][lr] = av.x; As[lk + 1][lr] = av.y;
    As[lk + 2][lr] = av.z; As[lk + 3][lr] = av.w;
    Bs[lk + 0][lr] = bv.x; Bs[lk + 1][lr] = bv.y;
    Bs[lk + 2][lr] = bv.z; Bs[lk + 3][lr] = bv.w;
    __syncthreads();
#pragma unroll
    for (int k = 0; k < 16; k++) {
      float a[4], b[4];
      *(float4*)a = *(const float4*)&As[k][ty * 4];
      *(float4*)b = *(const float4*)&Bs[k][tx * 4];
#pragma unroll
      for (int i = 0; i < 4; i++)
#pragma unroll
        for (int j = 0; j < 4; j++)
          acc[i][j] = fmaf(a[i], b[j], acc[i][j]);
    }
  }

  // Block covers exactly one (component, head): bn is a multiple of 64, D=64.
  const int comp = bn >> 10;          // 0:Q 1:K 2:V
  const int h = (bn & 1023) >> 6;
  float* dstBase = (comp == 0) ? g_Q : (comp == 1) ? g_K : g_V;
  dstBase += (size_t)h * (S * D);
  float4 bia = *(const float4*)&bias[bn + tx * 4];
#pragma unroll
  for (int i = 0; i < 4; i++) {
    int m = bm + ty * 4 + i;
    float4 o;
    o.x = acc[i][0] + bia.x;
    o.y = acc[i][1] + bia.y;
    o.z = acc[i][2] + bia.z;
    o.w = acc[i][3] + bia.w;
    *(float4*)&dstBase[(size_t)m * D + tx * 4] = o;
  }
}

// ---------------------------------------------------------------------------
// Zero the attention accumulator.
// ---------------------------------------------------------------------------
__global__ void zero_a_kernel() {
  size_t i = (size_t)blockIdx.x * blockDim.x + threadIdx.x;
  ((float4*)g_A)[i] = make_float4(0.f, 0.f, 0.f, 0.f);
}

// ---------------------------------------------------------------------------
// Flash attention over a dilated segment: positions pos(i) = i*dil, i in [0,n).
// One thread per query row (q,o in registers), 64-key smem tiles.
// Accumulates o/l into g_A (plain RMW; unique position per thread per launch).
// ---------------------------------------------------------------------------
__global__ __launch_bounds__(128) void flash_seg_kernel(int n, int dil) {
  __shared__ float Ks[64][64];
  __shared__ float Vs[64][64];
  const int h = blockIdx.y;
  const int qi = blockIdx.x * 128 + threadIdx.x;
  const float* Qh = g_Q + (size_t)h * (S * D);
  const float* Kh = g_K + (size_t)h * (S * D);
  const float* Vh = g_V + (size_t)h * (S * D);

  float q[64];
  {
    const float4* qp = (const float4*)(Qh + (size_t)qi * dil * D);
#pragma unroll
    for (int i = 0; i < 16; i++) {
      float4 v = qp[i];
      q[4 * i + 0] = v.x * 0.125f;   // fold 1/sqrt(D)
      q[4 * i + 1] = v.y * 0.125f;
      q[4 * i + 2] = v.z * 0.125f;
      q[4 * i + 3] = v.w * 0.125f;
    }
  }
  float o[64];
#pragma unroll
  for (int d = 0; d < 64; d++) o[d] = 0.f;
  float mval = -1e30f, l = 0.f;

  const int rr = threadIdx.x >> 4;   // 0..7
  const int c4 = threadIdx.x & 15;   // float4 column

  for (int kt = 0; kt < n; kt += 64) {
    __syncthreads();
#pragma unroll
    for (int p = 0; p < 8; p++) {
      int row = p * 8 + rr;
      size_t gsrc = (size_t)(kt + row) * dil * D;
      ((float4*)Ks[row])[c4] = *(const float4*)(Kh + gsrc + c4 * 4);
      ((float4*)Vs[row])[c4] = *(const float4*)(Vh + gsrc + c4 * 4);
    }
    __syncthreads();

    for (int j = 0; j < 64; j++) {
      const float4* kr = (const float4*)Ks[j];
      float4 sa = make_float4(0.f, 0.f, 0.f, 0.f);
#pragma unroll
      for (int d4 = 0; d4 < 16; d4++) {
        float4 kv = kr[d4];
        sa.x = fmaf(q[4 * d4 + 0], kv.x, sa.x);
        sa.y = fmaf(q[4 * d4 + 1], kv.y, sa.y);
        sa.z = fmaf(q[4 * d4 + 2], kv.z, sa.z);
        sa.w = fmaf(q[4 * d4 + 3], kv.w, sa.w);
      }
      float s = (sa.x + sa.y) + (sa.z + sa.w);
      const float4* vr = (const float4*)Vs[j];
      if (s <= mval) {                      // fast path: max unchanged
        float p = __expf(s - mval);
        l += p;
#pragma unroll
        for (int d4 = 0; d4 < 16; d4++) {
          float4 vv = vr[d4];
          o[4 * d4 + 0] = fmaf(p, vv.x, o[4 * d4 + 0]);
          o[4 * d4 + 1] = fmaf(p, vv.y, o[4 * d4 + 1]);
          o[4 * d4 + 2] = fmaf(p, vv.z, o[4 * d4 + 2]);
          o[4 * d4 + 3] = fmaf(p, vv.w, o[4 * d4 + 3]);
        }
      } else {                              // new max: rescale
        float alpha = __expf(mval - s);
        mval = s;
        l = fmaf(l, alpha, 1.0f);
#pragma unroll
        for (int d4 = 0; d4 < 16; d4++) {
          float4 vv = vr[d4];
          o[4 * d4 + 0] = fmaf(o[4 * d4 + 0], alpha, vv.x);
          o[4 * d4 + 1] = fmaf(o[4 * d4 + 1], alpha, vv.y);
          o[4 * d4 + 2] = fmaf(o[4 * d4 + 2], alpha, vv.z);
          o[4 * d4 + 3] = fmaf(o[4 * d4 + 3], alpha, vv.w);
        }
      }
    }
  }

  const float inv = 1.0f / l;
  float* dst = g_A + (size_t)(qi * dil) * E + h * D;
#pragma unroll
  for (int d = 0; d < 64; d++) dst[d] += o[d] * inv;
}

// ---------------------------------------------------------------------------
// Output projection: out[m][n] = (1/3)*sum_k g_A[m][k]*Wout[n][k] + bout[n]
// ---------------------------------------------------------------------------
__global__ __launch_bounds__(256) void out_gemm_kernel(
    const float* __restrict__ W, const float* __restrict__ bias,
    float* __restrict__ out) {
  __shared__ float As[16][64];
  __shared__ float Bs[16][64];
  const int bm = blockIdx.y * 64;
  const int bn = blockIdx.x * 64;
  const int tid = threadIdx.x;
  const int lr = tid >> 2;
  const int lk = (tid & 3) << 2;
  const int ty = tid >> 4;
  const int tx = tid & 15;

  float acc[4][4] = {};
  const float* Ap = g_A + (size_t)(bm + lr) * E + lk;
  const float* Wp = W + (size_t)(bn + lr) * E + lk;

  for (int k0 = 0; k0 < E; k0 += 16) {
    float4 av = *(const float4*)(Ap + k0);
    float4 bv = *(const float4*)(Wp + k0);
    __syncthreads();
    As[lk + 0][lr] = av.x; As[lk + 1][lr] = av.y;
    As[lk + 2][lr] = av.z; As[lk + 3][lr] = av.w;
    Bs[lk + 0][lr] = bv.x; Bs[lk + 1][lr] = bv.y;
    Bs[lk + 2][lr] = bv.z; Bs[lk + 3][lr] = bv.w;
    __syncthreads();
#pragma unroll
    for (int k = 0; k < 16; k++) {
      float a[4], b[4];
      *(float4*)a = *(const float4*)&As[k][ty * 4];
      *(float4*)b = *(const float4*)&Bs[k][tx * 4];
#pragma unroll
      for (int i = 0; i < 4; i++)
#pragma unroll
        for (int j = 0; j < 4; j++)
          acc[i][j] = fmaf(a[i], b[j], acc[i][j]);
    }
  }

  const float third = 1.0f / 3.0f;
  float4 bia = *(const float4*)&bias[bn + tx * 4];
#pragma unroll
  for (int i = 0; i < 4; i++) {
    int m = bm + ty * 4 + i;
    float4 o;
    o.x = fmaf(acc[i][0], third, bia.x);
    o.y = fmaf(acc[i][1], third, bia.y);
    o.z = fmaf(acc[i][2], third, bia.z);
    o.w = fmaf(acc[i][3], third, bia.w);
    *(float4*)&out[(size_t)m * E + bn + tx * 4] = o;
  }
}

// ---------------------------------------------------------------------------
extern "C" void kernel_launch(void* const* d_in, const int* in_sizes, int n_in,
                              void* d_out, int out_size) {
  const float* x     = (const float*)d_in[0];  // [S, E]
  const float* w_qkv = (const float*)d_in[1];  // [3E, E]
  const float* b_qkv = (const float*)d_in[2];  // [3E]
  const float* w_out = (const float*)d_in[3];  // [E, E]
  const float* b_out = (const float*)d_in[4];  // [E]
  float* out = (float*)d_out;                  // [S, E]

  qkv_gemm_kernel<<<dim3(E3 / 64, S / 64), 256>>>(x, w_qkv, b_qkv);

  // zero accumulator: S*E floats = 2M float4
  zero_a_kernel<<<(S * E / 4) / 256, 256>>>();

  // segments: (n positions, dilation)
  flash_seg_kernel<<<dim3(2048 / 128, H), 128>>>(2048, 1);  // seg_len 2048, dil 1
  flash_seg_kernel<<<dim3(4096 / 128, H), 128>>>(4096, 2);  // seg_len 4096, dil 2
  flash_seg_kernel<<<dim3(2048 / 128, H), 128>>>(2048, 4);  // seg_len 8192, dil 4

  out_gemm_kernel<<<dim3(E / 64, S / 64), 256>>>(w_out, b_out, out);
}

// round 3
// speedup vs baseline: 2.7881x; 2.7881x over previous
#include <cuda_runtime.h>

#define S 8192
#define E 1024
#define H 16
#define D 64
#define E3 3072

// Scratch (allocation-free rule: __device__ globals)
__device__ __align__(128) float g_Q[H * S * D];
__device__ __align__(128) float g_K[H * S * D];
__device__ __align__(128) float g_V[H * S * D];
__device__ __align__(128) float g_A[S * E];   // attention output accum, [s][h*D+d]

// ---------------------------------------------------------------------------
// helpers
// ---------------------------------------------------------------------------
__device__ __forceinline__ unsigned f2tf(float f) {
  unsigned u;
  asm("cvt.rna.tf32.f32 %0, %1;" : "=r"(u) : "f"(f));
  return u;
}

__device__ __forceinline__ void mma8(float* d, const unsigned* a, const unsigned* b) {
  asm volatile(
      "mma.sync.aligned.m16n8k8.row.col.f32.tf32.tf32.f32 "
      "{%0,%1,%2,%3},{%4,%5,%6,%7},{%8,%9},{%0,%1,%2,%3};"
      : "+f"(d[0]), "+f"(d[1]), "+f"(d[2]), "+f"(d[3])
      : "r"(a[0]), "r"(a[1]), "r"(a[2]), "r"(a[3]), "r"(b[0]), "r"(b[1]));
}

// ---------------------------------------------------------------------------
// tf32 GEMM, NT: C[m][n] = sum_k A[m][k]*B[n][k] (+bias epilogues)
// 128x128x16 tile, 256 threads (8 warps, 2x4), warp tile 64x32.
// smem holds fragment-permuted operands:
//  A atom (16m x 8k): 32 lanes x float4 ; B atom (8k x 8n): 32 lanes x float2
// mode 0: A = Agm (x), scatter to g_Q/g_K/g_V
// mode 1: A = g_A (device global, resolved IN DEVICE CODE), out = acc/3 + bias
// ---------------------------------------------------------------------------
__global__ __launch_bounds__(256) void gemm_tf32(
    const float* __restrict__ Agm_in, const float* __restrict__ Bgm,
    const float* __restrict__ bias, float* __restrict__ Cgm, int mode) {
  __shared__ float sA[2][2048];
  __shared__ float sB[2][2048];
  const int tid = threadIdx.x;
  const int lane = tid & 31;
  const int w = tid >> 5;
  const int wm = w & 1;      // 2 m-warps of 64
  const int wn = w >> 1;     // 4 n-warps of 32
  const int bm = blockIdx.y * 128;
  const int bn = blockIdx.x * 128;

  // NOTE: device-global scratch must be referenced from device code, not
  // passed from host (host-side &g_A is the host shadow; on GB300 ATS the
  // GPU silently reads host zeros instead of faulting).
  const float* Agm = (mode == 1) ? (const float*)g_A : Agm_in;

  float acc[4][4][4];
#pragma unroll
  for (int i = 0; i < 4; i++)
#pragma unroll
    for (int j = 0; j < 4; j++)
#pragma unroll
      for (int r = 0; r < 4; r++) acc[i][j][r] = 0.f;

  float4 ra[2], rb[2];

  auto ldg_tile = [&](int k0) {
#pragma unroll
    for (int i = 0; i < 2; i++) {
      int idx = tid + i * 256;     // 0..511
      int m = idx >> 2;
      int kq = idx & 3;
      ra[i] = *(const float4*)&Agm[(size_t)(bm + m) * E + k0 + kq * 4];
      rb[i] = *(const float4*)&Bgm[(size_t)(bn + m) * E + k0 + kq * 4];
    }
  };
  auto sts_tile = [&](int buf) {
#pragma unroll
    for (int i = 0; i < 2; i++) {
      int idx = tid + i * 256;
      int m = idx >> 2;
      int kq = idx & 3;
      float av[4] = {ra[i].x, ra[i].y, ra[i].z, ra[i].w};
      float bv[4] = {rb[i].x, rb[i].y, rb[i].z, rb[i].w};
#pragma unroll
      for (int e = 0; e < 4; e++) {
        int k = kq * 4 + e;
        int t = k >> 3;
        // A: atom = t*8 + m/16 ; lane' = ((m&7)<<2)|(k&3) ; reg = ((m>>3)&1)|(((k>>2)&1)<<1)
        sA[buf][(t * 8 + (m >> 4)) * 128 + (((m & 7) << 2) | (k & 3)) * 4 +
                (((m >> 3) & 1) | (((k >> 2) & 1) << 1))] =
            __uint_as_float(f2tf(av[e]));
        // B: atom = (m/8)*2 + t ; lane' = ((n&7)<<2)|(k&3) ; reg = (k>>2)&1
        sB[buf][(((m >> 3) << 1) | t) * 64 + (((m & 7) << 2) | (k & 3)) * 2 +
                ((k >> 2) & 1)] = __uint_as_float(f2tf(bv[e]));
      }
    }
  };

  ldg_tile(0);
  sts_tile(0);
  __syncthreads();

  const int NK = E / 16;
  for (int kt = 0; kt < NK; kt++) {
    int cur = kt & 1;
    if (kt + 1 < NK) ldg_tile((kt + 1) * 16);
#pragma unroll
    for (int ks = 0; ks < 2; ks++) {
      unsigned af[4][4];
#pragma unroll
      for (int ma = 0; ma < 4; ma++) {
        uint4 v = *(const uint4*)&sA[cur][(ks * 8 + wm * 4 + ma) * 128 + lane * 4];
        af[ma][0] = v.x; af[ma][1] = v.y; af[ma][2] = v.z; af[ma][3] = v.w;
      }
#pragma unroll
      for (int na = 0; na < 4; na++) {
        uint2 bf = *(const uint2*)&sB[cur][((((wn * 4 + na) << 1) | ks)) * 64 + lane * 2];
        unsigned bb[2] = {bf.x, bf.y};
#pragma unroll
        for (int ma = 0; ma < 4; ma++) mma8(acc[ma][na], af[ma], bb);
      }
    }
    if (kt + 1 < NK) {
      __syncthreads();
      sts_tile(cur ^ 1);
      __syncthreads();
    }
  }

  // epilogue
  const int r = lane >> 2;
  const int cq = (lane & 3) << 1;
  if (mode == 0) {
#pragma unroll
    for (int ma = 0; ma < 4; ma++) {
      int row = bm + wm * 64 + ma * 16 + r;
#pragma unroll
      for (int na = 0; na < 4; na++) {
        int col = bn + wn * 32 + na * 8 + cq;
        int comp = col >> 10;
        int hh = (col & 1023) >> 6;
        int dd = col & 63;
        float* base = (comp == 0) ? g_Q : (comp == 1) ? g_K : g_V;
        float2 b2 = *(const float2*)&bias[col];
        float2 v0, v1;
        v0.x = acc[ma][na][0] + b2.x; v0.y = acc[ma][na][1] + b2.y;
        v1.x = acc[ma][na][2] + b2.x; v1.y = acc[ma][na][3] + b2.y;
        *(float2*)&base[(size_t)hh * S * D + (size_t)row * 64 + dd] = v0;
        *(float2*)&base[(size_t)hh * S * D + (size_t)(row + 8) * 64 + dd] = v1;
      }
    }
  } else {
    const float third = 1.0f / 3.0f;
#pragma unroll
    for (int ma = 0; ma < 4; ma++) {
      int row = bm + wm * 64 + ma * 16 + r;
#pragma unroll
      for (int na = 0; na < 4; na++) {
        int col = bn + wn * 32 + na * 8 + cq;
        float2 b2 = *(const float2*)&bias[col];
        float2 v0, v1;
        v0.x = fmaf(acc[ma][na][0], third, b2.x);
        v0.y = fmaf(acc[ma][na][1], third, b2.y);
        v1.x = fmaf(acc[ma][na][2], third, b2.x);
        v1.y = fmaf(acc[ma][na][3], third, b2.y);
        *(float2*)&Cgm[(size_t)row * E + col] = v0;
        *(float2*)&Cgm[(size_t)(row + 8) * E + col] = v1;
      }
    }
  }
}

// ---------------------------------------------------------------------------
// Zero the attention accumulator.
// ---------------------------------------------------------------------------
__global__ void zero_a_kernel() {
  size_t i = (size_t)blockIdx.x * blockDim.x + threadIdx.x;
  ((float4*)g_A)[i] = make_float4(0.f, 0.f, 0.f, 0.f);
}

// ---------------------------------------------------------------------------
// FA2-style flash attention with tf32 mma. 128 queries/block (8 warps x 16
// rows), 64-key tiles. K/V staged in B-fragment-permuted smem; P re-layout
// via 512B/warp smem buffer. Accumulates o into g_A at dilated positions.
// ---------------------------------------------------------------------------
__global__ __launch_bounds__(256) void flash_tc(int n, int dil) {
  __shared__ float sK[4096];
  __shared__ float sV[4096];
  __shared__ float sP[8][128];
  const int tid = threadIdx.x;
  const int lane = tid & 31;
  const int w = tid >> 5;
  const int h = blockIdx.y;
  const int qbase = blockIdx.x * 128;
  const float* Qh = g_Q + (size_t)h * S * D;
  const float* Kh = g_K + (size_t)h * S * D;
  const float* Vh = g_V + (size_t)h * S * D;

  // Q fragments (scaled by 1/sqrt(D)=0.125), rows r0 / r0+8
  const int r0 = qbase + w * 16 + (lane >> 2);
  const int r1 = r0 + 8;
  unsigned qf[8][4];
  {
    const float* q0 = Qh + (size_t)r0 * dil * 64;
    const float* q1 = Qh + (size_t)r1 * dil * 64;
#pragma unroll
    for (int t = 0; t < 8; t++) {
      int d0 = t * 8 + (lane & 3);
      qf[t][0] = f2tf(q0[d0] * 0.125f);
      qf[t][1] = f2tf(q1[d0] * 0.125f);
      qf[t][2] = f2tf(q0[d0 + 4] * 0.125f);
      qf[t][3] = f2tf(q1[d0 + 4] * 0.125f);
    }
  }

  float oacc[8][4];
#pragma unroll
  for (int b = 0; b < 8; b++)
#pragma unroll
    for (int rr = 0; rr < 4; rr++) oacc[b][rr] = 0.f;
  float m0 = -1e30f, m1 = -1e30f, l0 = 0.f, l1 = 0.f;

  float4 rk[4], rv[4];
  auto ldg_kv = [&](int kt) {
    int base = kt * 64;
#pragma unroll
    for (int c = 0; c < 4; c++) {
      int idx = tid + c * 256;           // 0..1023
      int j = idx >> 4;
      int d4 = idx & 15;
      size_t off = (size_t)(base + j) * dil * 64 + d4 * 4;
      rk[c] = *(const float4*)&Kh[off];
      rv[c] = *(const float4*)&Vh[off];
    }
  };

  ldg_kv(0);
  const int ntiles = n >> 6;
  for (int kt = 0; kt < ntiles; kt++) {
    __syncthreads();
    // scatter K/V into fragment-permuted smem
#pragma unroll
    for (int c = 0; c < 4; c++) {
      int idx = tid + c * 256;
      int j = idx >> 4;
      int d4 = idx & 15;
      float kv[4] = {rk[c].x, rk[c].y, rk[c].z, rk[c].w};
      float vv[4] = {rv[c].x, rv[c].y, rv[c].z, rv[c].w};
#pragma unroll
      for (int e = 0; e < 4; e++) {
        int d = d4 * 4 + e;
        // K (S mma B-frag): atom(b=j/8, t=d/8), lane'=((j&7)<<2)|(d&3), reg=(d>>2)&1
        sK[((j >> 3) * 8 + (d >> 3)) * 64 + ((((j & 7) << 2) | (d & 3)) << 1) +
           ((d >> 2) & 1)] = __uint_as_float(f2tf(kv[e]));
        // V (PV mma B-frag): atom(b=d/8, t=j/8), lane'=((d&7)<<2)|(j&3), reg=(j>>2)&1
        sV[((d >> 3) * 8 + (j >> 3)) * 64 + ((((d & 7) << 2) | (j & 3)) << 1) +
           ((j >> 2) & 1)] = __uint_as_float(f2tf(vv[e]));
      }
    }
    __syncthreads();
    if (kt + 1 < ntiles) ldg_kv(kt + 1);

    // S = Q K^T for this tile: 8 key-atoms x 8 d-steps
    float sacc[8][4];
#pragma unroll
    for (int b = 0; b < 8; b++)
#pragma unroll
      for (int rr = 0; rr < 4; rr++) sacc[b][rr] = 0.f;
#pragma unroll
    for (int b = 0; b < 8; b++) {
#pragma unroll
      for (int t = 0; t < 8; t++) {
        uint2 bf = *(const uint2*)&sK[((b * 8 + t) * 32 + lane) * 2];
        unsigned bb[2] = {bf.x, bf.y};
        mma8(sacc[b], qf[t], bb);
      }
    }

    // online softmax on fragments (row r0 -> regs 0,1 ; row r1 -> regs 2,3)
    float mx0 = sacc[0][0], mx1 = sacc[0][2];
#pragma unroll
    for (int b = 0; b < 8; b++) {
      mx0 = fmaxf(mx0, fmaxf(sacc[b][0], sacc[b][1]));
      mx1 = fmaxf(mx1, fmaxf(sacc[b][2], sacc[b][3]));
    }
    mx0 = fmaxf(mx0, __shfl_xor_sync(0xffffffff, mx0, 1));
    mx0 = fmaxf(mx0, __shfl_xor_sync(0xffffffff, mx0, 2));
    mx1 = fmaxf(mx1, __shfl_xor_sync(0xffffffff, mx1, 1));
    mx1 = fmaxf(mx1, __shfl_xor_sync(0xffffffff, mx1, 2));
    float nm0 = fmaxf(m0, mx0), nm1 = fmaxf(m1, mx1);
    float al0 = __expf(m0 - nm0), al1 = __expf(m1 - nm1);
    m0 = nm0; m1 = nm1;
    float rs0 = 0.f, rs1 = 0.f;
#pragma unroll
    for (int b = 0; b < 8; b++) {
      float p0 = __expf(sacc[b][0] - nm0);
      float p1 = __expf(sacc[b][1] - nm0);
      float p2 = __expf(sacc[b][2] - nm1);
      float p3 = __expf(sacc[b][3] - nm1);
      sacc[b][0] = p0; sacc[b][1] = p1; sacc[b][2] = p2; sacc[b][3] = p3;
      rs0 += p0 + p1; rs1 += p2 + p3;
    }
    rs0 += __shfl_xor_sync(0xffffffff, rs0, 1);
    rs0 += __shfl_xor_sync(0xffffffff, rs0, 2);
    rs1 += __shfl_xor_sync(0xffffffff, rs1, 1);
    rs1 += __shfl_xor_sync(0xffffffff, rs1, 2);
    l0 = l0 * al0 + rs0;
    l1 = l1 * al1 + rs1;
#pragma unroll
    for (int b = 0; b < 8; b++) {
      oacc[b][0] *= al0; oacc[b][1] *= al0;
      oacc[b][2] *= al1; oacc[b][3] *= al1;
    }

    // O += P V : per key-atom t, re-layout P C-frag -> A-frag via smem
    const int rr_ = lane >> 2;
    const int j0 = (lane & 3) << 1;
    const int j1 = j0 + 1;
    const int lp0 = ((rr_ << 2) | (j0 & 3)) << 2;
    const int lp1 = ((rr_ << 2) | (j1 & 3)) << 2;
    const int rg0 = ((j0 >> 2) & 1) << 1;
    const int rg1 = ((j1 >> 2) & 1) << 1;
#pragma unroll
    for (int t = 0; t < 8; t++) {
      __syncwarp();
      sP[w][lp0 + rg0]     = __uint_as_float(f2tf(sacc[t][0]));
      sP[w][lp1 + rg1]     = __uint_as_float(f2tf(sacc[t][1]));
      sP[w][lp0 + rg0 + 1] = __uint_as_float(f2tf(sacc[t][2]));
      sP[w][lp1 + rg1 + 1] = __uint_as_float(f2tf(sacc[t][3]));
      __syncwarp();
      uint4 pv = *(const uint4*)&sP[w][lane * 4];
      unsigned pf[4] = {pv.x, pv.y, pv.z, pv.w};
#pragma unroll
      for (int b = 0; b < 8; b++) {
        uint2 bf = *(const uint2*)&sV[((b * 8 + t) * 32 + lane) * 2];
        unsigned bb[2] = {bf.x, bf.y};
        mma8(oacc[b], pf, bb);
      }
    }
  }

  // epilogue: o/l accumulated into g_A at dilated positions
  const float inv0 = 1.0f / l0;
  const float inv1 = 1.0f / l1;
  float* a0 = g_A + (size_t)r0 * dil * E + h * 64;
  float* a1 = g_A + (size_t)r1 * dil * E + h * 64;
#pragma unroll
  for (int b = 0; b < 8; b++) {
    int dd = b * 8 + ((lane & 3) << 1);
    float2 v0 = *(float2*)&a0[dd];
    v0.x += oacc[b][0] * inv0;
    v0.y += oacc[b][1] * inv0;
    *(float2*)&a0[dd] = v0;
    float2 v1 = *(float2*)&a1[dd];
    v1.x += oacc[b][2] * inv1;
    v1.y += oacc[b][3] * inv1;
    *(float2*)&a1[dd] = v1;
  }
}

// ---------------------------------------------------------------------------
extern "C" void kernel_launch(void* const* d_in, const int* in_sizes, int n_in,
                              void* d_out, int out_size) {
  const float* x     = (const float*)d_in[0];  // [S, E]
  const float* w_qkv = (const float*)d_in[1];  // [3E, E]
  const float* b_qkv = (const float*)d_in[2];  // [3E]
  const float* w_out = (const float*)d_in[3];  // [E, E]
  const float* b_out = (const float*)d_in[4];  // [E]
  float* out = (float*)d_out;                  // [S, E]

  gemm_tf32<<<dim3(E3 / 128, S / 128), 256>>>(x, w_qkv, b_qkv, nullptr, 0);

  zero_a_kernel<<<(S * E / 4) / 256, 256>>>();

  flash_tc<<<dim3(2048 / 128, H), 256>>>(2048, 1);  // seg_len 2048, dil 1
  flash_tc<<<dim3(4096 / 128, H), 256>>>(4096, 2);  // seg_len 4096, dil 2
  flash_tc<<<dim3(2048 / 128, H), 256>>>(2048, 4);  // seg_len 8192, dil 4

  gemm_tf32<<<dim3(E / 128, S / 128), 256>>>(nullptr, w_out, b_out, out, 1);
}

// round 4
// speedup vs baseline: 7.3185x; 2.6249x over previous
#include <cuda_runtime.h>
#include <cuda_fp16.h>

#define S 8192
#define E 1024
#define H 16
#define D 64
#define E3 3072

// Scratch (allocation-free rule: __device__ globals, referenced ONLY in device code)
__device__ __align__(128) __half g_Qh[H * S * D];   // pre-scaled by 1/sqrt(D)
__device__ __align__(128) __half g_Kh[H * S * D];
__device__ __align__(128) __half g_Vh[H * S * D];
__device__ __align__(128) float  g_A[S * E];        // attention output accum (fp32)

// ---------------------------------------------------------------------------
// helpers
// ---------------------------------------------------------------------------
__device__ __forceinline__ unsigned packh2(float lo, float hi) {
  __half2 h = __float22half2_rn(make_float2(lo, hi));
  return *reinterpret_cast<unsigned*>(&h);
}

__device__ __forceinline__ void mma16(float* d, const unsigned* a, unsigned b0,
                                      unsigned b1) {
  asm volatile(
      "mma.sync.aligned.m16n8k16.row.col.f32.f16.f16.f32 "
      "{%0,%1,%2,%3},{%4,%5,%6,%7},{%8,%9},{%0,%1,%2,%3};"
      : "+f"(d[0]), "+f"(d[1]), "+f"(d[2]), "+f"(d[3])
      : "r"(a[0]), "r"(a[1]), "r"(a[2]), "r"(a[3]), "r"(b0), "r"(b1));
}

// ---------------------------------------------------------------------------
// fp16 GEMM, NT: C[m][n] = sum_k A[m][k]*B[n][k] (+bias epilogues)
// 128x128x32 tile, 256 threads (8 warps, 2x4), warp tile 64x32, fp32 accum.
// smem fragment-permuted (m16n8k16 atoms):
//  A atom (16m x 16k): 32 lanes x uint4 ; B atom (16k x 8n): 32 lanes x uint2
// mode 0: A = Agm (x), scatter fp16 to g_Qh (x0.125) / g_Kh / g_Vh
// mode 1: A = g_A (device-resolved), out = acc/3 + bias (fp32)
// ---------------------------------------------------------------------------
__global__ __launch_bounds__(256) void gemm_fp16(
    const float* __restrict__ Agm_in, const float* __restrict__ Bgm,
    const float* __restrict__ bias, float* __restrict__ Cgm, int mode) {
  __shared__ unsigned sA[2][2048];   // 128m x 32k halves = 2048 uint
  __shared__ unsigned sB[2][2048];
  const int tid = threadIdx.x;
  const int lane = tid & 31;
  const int w = tid >> 5;
  const int wm = w & 1;
  const int wn = w >> 1;
  const int bm = blockIdx.y * 128;
  const int bn = blockIdx.x * 128;

  const float* Agm = (mode == 1) ? (const float*)g_A : Agm_in;

  float acc[4][4][4];
#pragma unroll
  for (int i = 0; i < 4; i++)
#pragma unroll
    for (int j = 0; j < 4; j++)
#pragma unroll
      for (int r = 0; r < 4; r++) acc[i][j][r] = 0.f;

  float4 ra[4], rb[4];

  auto ldg_tile = [&](int k0) {
#pragma unroll
    for (int i = 0; i < 4; i++) {
      int idx = tid + i * 256;       // 0..1023
      int m = idx >> 3;              // 0..127
      int kq = idx & 7;              // k = k0 + kq*4
      ra[i] = *(const float4*)&Agm[(size_t)(bm + m) * E + k0 + kq * 4];
      rb[i] = *(const float4*)&Bgm[(size_t)(bn + m) * E + k0 + kq * 4];
    }
  };
  auto sts_tile = [&](int buf) {
#pragma unroll
    for (int i = 0; i < 4; i++) {
      int idx = tid + i * 256;
      int m = idx >> 3;
      int kq = idx & 7;
#pragma unroll
      for (int p = 0; p < 2; p++) {
        int k2 = kq * 2 + p;         // half2 index along k (0..15)
        float alo = p ? ra[i].z : ra[i].x;
        float ahi = p ? ra[i].w : ra[i].y;
        float blo = p ? rb[i].z : rb[i].x;
        float bhi = p ? rb[i].w : rb[i].y;
        // A: atom = (k2>>3)*8 + m/16 ; lane' = (m&7)*4 + (k2&3) ;
        //    reg = ((m>>3)&1) | (((k2>>2)&1)<<1)
        sA[buf][((k2 >> 3) * 8 + (m >> 4)) * 128 +
                (((m & 7) << 2) | (k2 & 3)) * 4 +
                (((m >> 3) & 1) | (((k2 >> 2) & 1) << 1))] = packh2(alo, ahi);
        // B: atom = (n/8)*2 + (k2>>3) ; lane' = (n&7)*4 + (k2&3) ; reg = (k2>>2)&1
        sB[buf][(((m >> 3) << 1) | (k2 >> 3)) * 64 +
                (((m & 7) << 2) | (k2 & 3)) * 2 + ((k2 >> 2) & 1)] =
            packh2(blo, bhi);
      }
    }
  };

  ldg_tile(0);
  sts_tile(0);
  __syncthreads();

  const int NK = E / 32;
  for (int kt = 0; kt < NK; kt++) {
    int cur = kt & 1;
    if (kt + 1 < NK) ldg_tile((kt + 1) * 32);
#pragma unroll
    for (int ks = 0; ks < 2; ks++) {
      unsigned af[4][4];
#pragma unroll
      for (int ma = 0; ma < 4; ma++) {
        uint4 v = *(const uint4*)&sA[cur][(ks * 8 + wm * 4 + ma) * 128 + lane * 4];
        af[ma][0] = v.x; af[ma][1] = v.y; af[ma][2] = v.z; af[ma][3] = v.w;
      }
#pragma unroll
      for (int na = 0; na < 4; na++) {
        uint2 bf = *(const uint2*)&sB[cur][(((wn * 4 + na) << 1) | ks) * 64 + lane * 2];
#pragma unroll
        for (int ma = 0; ma < 4; ma++) mma16(acc[ma][na], af[ma], bf.x, bf.y);
      }
    }
    if (kt + 1 < NK) {
      __syncthreads();
      sts_tile(cur ^ 1);
      __syncthreads();
    }
  }

  const int r = lane >> 2;
  const int cq = (lane & 3) << 1;
  if (mode == 0) {
#pragma unroll
    for (int ma = 0; ma < 4; ma++) {
      int row = bm + wm * 64 + ma * 16 + r;
#pragma unroll
      for (int na = 0; na < 4; na++) {
        int col = bn + wn * 32 + na * 8 + cq;
        int comp = col >> 10;
        int hh = (col & 1023) >> 6;
        int dd = col & 63;
        __half* base = (comp == 0) ? g_Qh : (comp == 1) ? g_Kh : g_Vh;
        float sc = (comp == 0) ? 0.125f : 1.0f;   // fold 1/sqrt(D) into Q
        float2 b2 = *(const float2*)&bias[col];
        unsigned v0 = packh2((acc[ma][na][0] + b2.x) * sc,
                             (acc[ma][na][1] + b2.y) * sc);
        unsigned v1 = packh2((acc[ma][na][2] + b2.x) * sc,
                             (acc[ma][na][3] + b2.y) * sc);
        *(unsigned*)(base + (size_t)hh * S * D + (size_t)row * 64 + dd) = v0;
        *(unsigned*)(base + (size_t)hh * S * D + (size_t)(row + 8) * 64 + dd) = v1;
      }
    }
  } else {
    const float third = 1.0f / 3.0f;
#pragma unroll
    for (int ma = 0; ma < 4; ma++) {
      int row = bm + wm * 64 + ma * 16 + r;
#pragma unroll
      for (int na = 0; na < 4; na++) {
        int col = bn + wn * 32 + na * 8 + cq;
        float2 b2 = *(const float2*)&bias[col];
        float2 v0, v1;
        v0.x = fmaf(acc[ma][na][0], third, b2.x);
        v0.y = fmaf(acc[ma][na][1], third, b2.y);
        v1.x = fmaf(acc[ma][na][2], third, b2.x);
        v1.y = fmaf(acc[ma][na][3], third, b2.y);
        *(float2*)&Cgm[(size_t)row * E + col] = v0;
        *(float2*)&Cgm[(size_t)(row + 8) * E + col] = v1;
      }
    }
  }
}

// ---------------------------------------------------------------------------
// Zero the attention accumulator.
// ---------------------------------------------------------------------------
__global__ void zero_a_kernel() {
  size_t i = (size_t)blockIdx.x * blockDim.x + threadIdx.x;
  ((float4*)g_A)[i] = make_float4(0.f, 0.f, 0.f, 0.f);
}

// ---------------------------------------------------------------------------
// FA2 flash attention, fp16 m16n8k16. 128 queries/block (8 warps x 16 rows),
// 64-key tiles. K staged as half2-pairs along d ([d2][j]); V as half2-pairs
// along keys ([j2][d]). S C-frag == P A-frag (no relayout). fp32 softmax/accum.
// ---------------------------------------------------------------------------
__global__ __launch_bounds__(256, 2) void flash_fp16(int n, int dil) {
  __shared__ unsigned sK[32 * 72];   // [d2 0..31][j 0..63 pad 72]
  __shared__ unsigned sV[32 * 72];   // [j2 0..31][d 0..63 pad 72]
  const int tid = threadIdx.x;
  const int lane = tid & 31;
  const int w = tid >> 5;
  const int h = blockIdx.y;
  const int qbase = blockIdx.x * 128;
  const __half* Qh = g_Qh + (size_t)h * S * D;
  const __half* Kh = g_Kh + (size_t)h * S * D;
  const __half* Vh = g_Vh + (size_t)h * S * D;

  // Q fragments (already scaled), rows r0 / r0+8
  const int r0 = qbase + w * 16 + (lane >> 2);
  const int r1 = r0 + 8;
  unsigned qf[4][4];
  {
    const unsigned* q0u = (const unsigned*)(Qh + (size_t)r0 * dil * 64);
    const unsigned* q1u = (const unsigned*)(Qh + (size_t)r1 * dil * 64);
#pragma unroll
    for (int t = 0; t < 4; t++) {
      int x = t * 8 + (lane & 3);
      qf[t][0] = q0u[x];
      qf[t][1] = q1u[x];
      qf[t][2] = q0u[x + 4];
      qf[t][3] = q1u[x + 4];
    }
  }

  float oacc[8][4];
#pragma unroll
  for (int b = 0; b < 8; b++)
#pragma unroll
    for (int rr = 0; rr < 4; rr++) oacc[b][rr] = 0.f;
  float m0 = -1e30f, m1 = -1e30f, l0 = 0.f, l1 = 0.f;

  // load assignments
  const int kj = tid & 63;          // K: row j, d8 and d8+4
  const int kd8 = tid >> 6;         // 0..3
  const int vj2 = tid >> 3;         // V: key pair 0..31
  const int vd8 = tid & 7;          // 0..7

  uint4 rk0, rk1, rv0, rv1;
  auto ldg_kv = [&](int kt) {
    int base = kt * 64;
    const uint4* Kr = (const uint4*)(Kh + (size_t)(base + kj) * dil * 64);
    rk0 = Kr[kd8];
    rk1 = Kr[kd8 + 4];
    const uint4* Vr0 = (const uint4*)(Vh + (size_t)(base + 2 * vj2) * dil * 64);
    const uint4* Vr1 = (const uint4*)(Vh + (size_t)(base + 2 * vj2 + 1) * dil * 64);
    rv0 = Vr0[vd8];
    rv1 = Vr1[vd8];
  };

  ldg_kv(0);
  const int ntiles = n >> 6;
  for (int kt = 0; kt < ntiles; kt++) {
    __syncthreads();
    // K: uint components are already (d,d+1) half2 pairs -> rows d2, col j
    {
      int b0 = (kd8 * 4) * 72 + kj;
      sK[b0] = rk0.x; sK[b0 + 72] = rk0.y; sK[b0 + 144] = rk0.z; sK[b0 + 216] = rk0.w;
      int b1 = ((kd8 + 4) * 4) * 72 + kj;
      sK[b1] = rk1.x; sK[b1 + 72] = rk1.y; sK[b1 + 144] = rk1.z; sK[b1 + 216] = rk1.w;
    }
    // V: interleave rows 2j2 / 2j2+1 into half2-pairs along keys
    {
      unsigned o0 = __byte_perm(rv0.x, rv1.x, 0x5410);
      unsigned o1 = __byte_perm(rv0.x, rv1.x, 0x7632);
      unsigned o2 = __byte_perm(rv0.y, rv1.y, 0x5410);
      unsigned o3 = __byte_perm(rv0.y, rv1.y, 0x7632);
      unsigned o4 = __byte_perm(rv0.z, rv1.z, 0x5410);
      unsigned o5 = __byte_perm(rv0.z, rv1.z, 0x7632);
      unsigned o6 = __byte_perm(rv0.w, rv1.w, 0x5410);
      unsigned o7 = __byte_perm(rv0.w, rv1.w, 0x7632);
      *(uint4*)&sV[vj2 * 72 + vd8 * 8] = make_uint4(o0, o1, o2, o3);
      *(uint4*)&sV[vj2 * 72 + vd8 * 8 + 4] = make_uint4(o4, o5, o6, o7);
    }
    __syncthreads();
    if (kt + 1 < ntiles) ldg_kv(kt + 1);

    // S = Q K^T : 8 key-atoms x 4 k16-steps
    float sacc[8][4];
#pragma unroll
    for (int b = 0; b < 8; b++)
#pragma unroll
      for (int rr = 0; rr < 4; rr++) sacc[b][rr] = 0.f;
    const int cidx0 = lane >> 2;
    const int ridx0 = lane & 3;
#pragma unroll
    for (int b = 0; b < 8; b++) {
      int c = b * 8 + cidx0;
#pragma unroll
      for (int t = 0; t < 4; t++) {
        int rdx = t * 8 + ridx0;
        mma16(sacc[b], qf[t], sK[rdx * 72 + c], sK[(rdx + 4) * 72 + c]);
      }
    }

    // online softmax (fp32)
    float mx0 = sacc[0][0], mx1 = sacc[0][2];
#pragma unroll
    for (int b = 0; b < 8; b++) {
      mx0 = fmaxf(mx0, fmaxf(sacc[b][0], sacc[b][1]));
      mx1 = fmaxf(mx1, fmaxf(sacc[b][2], sacc[b][3]));
    }
    mx0 = fmaxf(mx0, __shfl_xor_sync(0xffffffff, mx0, 1));
    mx0 = fmaxf(mx0, __shfl_xor_sync(0xffffffff, mx0, 2));
    mx1 = fmaxf(mx1, __shfl_xor_sync(0xffffffff, mx1, 1));
    mx1 = fmaxf(mx1, __shfl_xor_sync(0xffffffff, mx1, 2));
    float nm0 = fmaxf(m0, mx0), nm1 = fmaxf(m1, mx1);
    float al0 = __expf(m0 - nm0), al1 = __expf(m1 - nm1);
    m0 = nm0; m1 = nm1;
    float rs0 = 0.f, rs1 = 0.f;
#pragma unroll
    for (int b = 0; b < 8; b++) {
      float p0 = __expf(sacc[b][0] - nm0);
      float p1 = __expf(sacc[b][1] - nm0);
      float p2 = __expf(sacc[b][2] - nm1);
      float p3 = __expf(sacc[b][3] - nm1);
      sacc[b][0] = p0; sacc[b][1] = p1; sacc[b][2] = p2; sacc[b][3] = p3;
      rs0 += p0 + p1; rs1 += p2 + p3;
    }
    rs0 += __shfl_xor_sync(0xffffffff, rs0, 1);
    rs0 += __shfl_xor_sync(0xffffffff, rs0, 2);
    rs1 += __shfl_xor_sync(0xffffffff, rs1, 1);
    rs1 += __shfl_xor_sync(0xffffffff, rs1, 2);
    l0 = l0 * al0 + rs0;
    l1 = l1 * al1 + rs1;
#pragma unroll
    for (int b = 0; b < 8; b++) {
      oacc[b][0] *= al0; oacc[b][1] *= al0;
      oacc[b][2] *= al1; oacc[b][3] *= al1;
    }

    // P A-fragments: C-frag layout == A-frag layout (no lane movement)
    unsigned pf[4][4];
#pragma unroll
    for (int t = 0; t < 4; t++) {
      pf[t][0] = packh2(sacc[2 * t][0], sacc[2 * t][1]);
      pf[t][1] = packh2(sacc[2 * t][2], sacc[2 * t][3]);
      pf[t][2] = packh2(sacc[2 * t + 1][0], sacc[2 * t + 1][1]);
      pf[t][3] = packh2(sacc[2 * t + 1][2], sacc[2 * t + 1][3]);
    }

    // O += P V : 8 d-atoms x 4 key16-steps
#pragma unroll
    for (int b = 0; b < 8; b++) {
      int c = b * 8 + cidx0;
#pragma unroll
      for (int t = 0; t < 4; t++) {
        int rdx = t * 8 + ridx0;
        mma16(oacc[b], pf[t], sV[rdx * 72 + c], sV[(rdx + 4) * 72 + c]);
      }
    }
  }

  // epilogue: o/l accumulated into g_A at dilated positions (fp32 RMW)
  const float inv0 = 1.0f / l0;
  const float inv1 = 1.0f / l1;
  float* a0 = g_A + (size_t)r0 * dil * E + h * 64;
  float* a1 = g_A + (size_t)r1 * dil * E + h * 64;
#pragma unroll
  for (int b = 0; b < 8; b++) {
    int dd = b * 8 + ((lane & 3) << 1);
    float2 v0 = *(float2*)&a0[dd];
    v0.x += oacc[b][0] * inv0;
    v0.y += oacc[b][1] * inv0;
    *(float2*)&a0[dd] = v0;
    float2 v1 = *(float2*)&a1[dd];
    v1.x += oacc[b][2] * inv1;
    v1.y += oacc[b][3] * inv1;
    *(float2*)&a1[dd] = v1;
  }
}

// ---------------------------------------------------------------------------
extern "C" void kernel_launch(void* const* d_in, const int* in_sizes, int n_in,
                              void* d_out, int out_size) {
  const float* x     = (const float*)d_in[0];  // [S, E]
  const float* w_qkv = (const float*)d_in[1];  // [3E, E]
  const float* b_qkv = (const float*)d_in[2];  // [3E]
  const float* w_out = (const float*)d_in[3];  // [E, E]
  const float* b_out = (const float*)d_in[4];  // [E]
  float* out = (float*)d_out;                  // [S, E]

  gemm_fp16<<<dim3(E3 / 128, S / 128), 256>>>(x, w_qkv, b_qkv, nullptr, 0);

  zero_a_kernel<<<(S * E / 4) / 256, 256>>>();

  flash_fp16<<<dim3(2048 / 128, H), 256>>>(2048, 1);  // seg_len 2048, dil 1
  flash_fp16<<<dim3(4096 / 128, H), 256>>>(4096, 2);  // seg_len 4096, dil 2
  flash_fp16<<<dim3(2048 / 128, H), 256>>>(2048, 4);  // seg_len 8192, dil 4

  gemm_fp16<<<dim3(E / 128, S / 128), 256>>>(nullptr, w_out, b_out, out, 1);
}